// round 9
// baseline (speedup 1.0000x reference)
#include <cuda_runtime.h>
#include <cuda_bf16.h>
#include <math.h>

// Problem constants (fixed by the dataset: B=2, S=2048, D=1024, H=16, hd=64)
#define DMODEL 1024
#define NHEAD  16
#define HD     64

// Scratch (allocation-free rule: __device__ globals). M*D = 4096*1024 floats.
__device__ float g_q [4194304];
__device__ float g_k [4194304];
__device__ float g_v [4194304];
__device__ float g_wv[4194304];

// ---------------------------------------------------------------------------
// Generic C[M,N] = A[M,K] @ B[N,K]^T + bias.  64x64 tile, k-chunk 16,
// 256 threads, 4x4 register blocking, k-major smem tiles for float4 LDS.
// M, N, K must be multiples of 64/64/16 (true here).
// ---------------------------------------------------------------------------
__global__ __launch_bounds__(256) void gemm_tn(
    const float* __restrict__ A, const float* __restrict__ B,
    const float* __restrict__ bias, float* __restrict__ C,
    int M, int N, int K)
{
    __shared__ float As[16][64];
    __shared__ float Bs[16][64];

    const int tid = threadIdx.x;
    const int tx = tid & 15;
    const int ty = tid >> 4;
    const int m0 = blockIdx.y * 64;
    const int n0 = blockIdx.x * 64;

    const int lrow = tid >> 2;        // 0..63
    const int lk   = (tid & 3) * 4;   // 0,4,8,12

    const float* Ap = A + (size_t)(m0 + lrow) * K + lk;
    const float* Bp = B + (size_t)(n0 + lrow) * K + lk;

    float acc[4][4];
#pragma unroll
    for (int i = 0; i < 4; i++)
#pragma unroll
        for (int j = 0; j < 4; j++) acc[i][j] = 0.f;

    for (int k0 = 0; k0 < K; k0 += 16) {
        float4 av = *(const float4*)(Ap + k0);
        float4 bv = *(const float4*)(Bp + k0);
        __syncthreads();
        As[lk+0][lrow] = av.x; As[lk+1][lrow] = av.y;
        As[lk+2][lrow] = av.z; As[lk+3][lrow] = av.w;
        Bs[lk+0][lrow] = bv.x; Bs[lk+1][lrow] = bv.y;
        Bs[lk+2][lrow] = bv.z; Bs[lk+3][lrow] = bv.w;
        __syncthreads();
#pragma unroll
        for (int kk = 0; kk < 16; kk++) {
            float4 a = *(const float4*)&As[kk][ty*4];
            float4 b = *(const float4*)&Bs[kk][tx*4];
            acc[0][0] += a.x*b.x; acc[0][1] += a.x*b.y; acc[0][2] += a.x*b.z; acc[0][3] += a.x*b.w;
            acc[1][0] += a.y*b.x; acc[1][1] += a.y*b.y; acc[1][2] += a.y*b.z; acc[1][3] += a.y*b.w;
            acc[2][0] += a.z*b.x; acc[2][1] += a.z*b.y; acc[2][2] += a.z*b.z; acc[2][3] += a.z*b.w;
            acc[3][0] += a.w*b.x; acc[3][1] += a.w*b.y; acc[3][2] += a.w*b.z; acc[3][3] += a.w*b.w;
        }
    }

    float b0 = 0.f, b1 = 0.f, b2 = 0.f, b3 = 0.f;
    if (bias) {
        float4 bb = *(const float4*)(bias + n0 + tx*4);
        b0 = bb.x; b1 = bb.y; b2 = bb.z; b3 = bb.w;
    }
#pragma unroll
    for (int i = 0; i < 4; i++) {
        float4 r4 = make_float4(acc[i][0] + b0, acc[i][1] + b1,
                                acc[i][2] + b2, acc[i][3] + b3);
        *(float4*)&C[(size_t)(m0 + ty*4 + i) * N + n0 + tx*4] = r4;
    }
}

// ---------------------------------------------------------------------------
// RoPE + hd^-0.25 scaling, applied in place to q and k.
// One thread per (token m, head h, pair index i<32).
// ---------------------------------------------------------------------------
__global__ void rope_scale_kernel(float* __restrict__ q, float* __restrict__ k,
                                  const int* __restrict__ pos, int total)
{
    int idx = blockIdx.x * blockDim.x + threadIdx.x;
    if (idx >= total) return;
    int i = idx & 31;
    int h = (idx >> 5) & (NHEAD - 1);
    int m = idx >> 9;                 // token index (b*S + s)

    int p = pos[m];
    // inv_freq = 10000^(-i/32) = 2^(-i * log2(10000)/32)
    float freq = (float)p * exp2f(-(float)i * 0.4152410118609203f);
    float sn, cs;
    sincosf(freq, &sn, &cs);
    const float scale = 0.35355339059327373f;   // 64^-0.25

    size_t base = (size_t)m * DMODEL + h * HD + i;
    float q0 = q[base], q1 = q[base + 32];
    q[base]      = (q0 * cs - q1 * sn) * scale;
    q[base + 32] = (q1 * cs + q0 * sn) * scale;
    float k0 = k[base], k1 = k[base + 32];
    k[base]      = (k0 * cs - k1 * sn) * scale;
    k[base + 32] = (k1 * cs + k0 * sn) * scale;
}

// ---------------------------------------------------------------------------
// Flash-style attention: per block one (b, h, 64-query tile).
// Streams raw scores to qk (the second kernel output) while doing online
// softmax + PV accumulation. wv written in [B,S,D] layout for the O GEMM.
// ---------------------------------------------------------------------------
struct AttnSmem {
    float Qt[64][64];      // [d][q]  (transposed for outer-product LDS.128)
    float Kt[64][64];      // [d][kcol]
    float Vs[64][64];      // [k][d]
    float Ps[64][64];      // [q][k]  (row-major; PV reads a-operand as broadcast)
    float red[64][17];     // row reduction scratch (padded)
    float m_s[64], l_s[64], alpha_s[64];
    int   msk[64];
};

__global__ __launch_bounds__(256) void attn_kernel(
    const float* __restrict__ qg, const float* __restrict__ kg,
    const float* __restrict__ vg, const int* __restrict__ mask,
    float* __restrict__ qk, float* __restrict__ wv, int S)
{
    extern __shared__ char smraw[];
    AttnSmem* sm = (AttnSmem*)smraw;

    const int tid = threadIdx.x;
    const int tx = tid & 15;
    const int ty = tid >> 4;
    const int b  = blockIdx.z;
    const int h  = blockIdx.y;
    const int q0 = blockIdx.x * 64;

    // Load Q tile transposed: Qt[d][qrow]
    size_t baseQ = ((size_t)b * S + q0) * DMODEL + h * HD;
#pragma unroll
    for (int it = 0; it < 4; it++) {
        int e  = tid + it * 256;
        int r  = e >> 4;
        int c4 = (e & 15) << 2;
        float4 v4 = *(const float4*)(qg + baseQ + (size_t)r * DMODEL + c4);
        sm->Qt[c4+0][r] = v4.x; sm->Qt[c4+1][r] = v4.y;
        sm->Qt[c4+2][r] = v4.z; sm->Qt[c4+3][r] = v4.w;
    }
    if (tid < 64) { sm->m_s[tid] = -INFINITY; sm->l_s[tid] = 0.f; }

    float o[4][4];
#pragma unroll
    for (int i = 0; i < 4; i++)
#pragma unroll
        for (int j = 0; j < 4; j++) o[i][j] = 0.f;

    for (int kt = 0; kt < S; kt += 64) {
        __syncthreads();   // previous iter done reading Kt/Vs/Ps; Q loaded (iter 0)
        size_t baseKV = ((size_t)b * S + kt) * DMODEL + h * HD;
#pragma unroll
        for (int it = 0; it < 4; it++) {
            int e  = tid + it * 256;
            int r  = e >> 4;
            int c4 = (e & 15) << 2;
            float4 k4 = *(const float4*)(kg + baseKV + (size_t)r * DMODEL + c4);
            sm->Kt[c4+0][r] = k4.x; sm->Kt[c4+1][r] = k4.y;
            sm->Kt[c4+2][r] = k4.z; sm->Kt[c4+3][r] = k4.w;
            float4 v4 = *(const float4*)(vg + baseKV + (size_t)r * DMODEL + c4);
            *(float4*)&sm->Vs[r][c4] = v4;
        }
        if (tid < 64) sm->msk[tid] = mask[(size_t)b * S + kt + tid];
        __syncthreads();

        // S tile: s[qi][kj] = sum_d Q[qi][d] * K[kj][d]
        float s[4][4];
#pragma unroll
        for (int i = 0; i < 4; i++)
#pragma unroll
            for (int j = 0; j < 4; j++) s[i][j] = 0.f;
#pragma unroll 8
        for (int d = 0; d < 64; d++) {
            float4 a  = *(const float4*)&sm->Qt[d][ty*4];
            float4 bb = *(const float4*)&sm->Kt[d][tx*4];
            s[0][0] += a.x*bb.x; s[0][1] += a.x*bb.y; s[0][2] += a.x*bb.z; s[0][3] += a.x*bb.w;
            s[1][0] += a.y*bb.x; s[1][1] += a.y*bb.y; s[1][2] += a.y*bb.z; s[1][3] += a.y*bb.w;
            s[2][0] += a.z*bb.x; s[2][1] += a.z*bb.y; s[2][2] += a.z*bb.z; s[2][3] += a.z*bb.w;
            s[3][0] += a.w*bb.x; s[3][1] += a.w*bb.y; s[3][2] += a.w*bb.z; s[3][3] += a.w*bb.w;
        }

        // mask, write raw scores to qk, partial row-max
#pragma unroll
        for (int i = 0; i < 4; i++) {
            float pm = -INFINITY;
#pragma unroll
            for (int j = 0; j < 4; j++) {
                if (sm->msk[tx*4 + j] == 0) s[i][j] = -INFINITY;
                pm = fmaxf(pm, s[i][j]);
            }
            if (qk) {
                size_t qr = (size_t)q0 + ty*4 + i;
                *(float4*)&qk[(((size_t)(b * NHEAD + h)) * S + qr) * S + kt + tx*4] =
                    make_float4(s[i][0], s[i][1], s[i][2], s[i][3]);
            }
            sm->red[ty*4 + i][tx] = pm;
        }
        __syncthreads();

        if (tid < 64) {
            float mx = sm->red[tid][0];
#pragma unroll
            for (int t = 1; t < 16; t++) mx = fmaxf(mx, sm->red[tid][t]);
            float mo = sm->m_s[tid];
            float mn = fmaxf(mo, mx);
            sm->alpha_s[tid] = (mo == -INFINITY) ? 0.f : __expf(mo - mn);
            sm->m_s[tid] = mn;
        }
        __syncthreads();

        // p = exp(s - m), store Ps, partial row sums, rescale O
#pragma unroll
        for (int i = 0; i < 4; i++) {
            int r = ty*4 + i;
            float mn = sm->m_s[r];
            float msub = (mn == -INFINITY) ? 0.f : mn;
            float al = sm->alpha_s[r];
            float p0 = __expf(s[i][0] - msub);
            float p1 = __expf(s[i][1] - msub);
            float p2 = __expf(s[i][2] - msub);
            float p3 = __expf(s[i][3] - msub);
            *(float4*)&sm->Ps[r][tx*4] = make_float4(p0, p1, p2, p3);
            sm->red[r][tx] = p0 + p1 + p2 + p3;
            o[i][0] *= al; o[i][1] *= al; o[i][2] *= al; o[i][3] *= al;
        }
        __syncthreads();

        if (tid < 64) {
            float sum = sm->red[tid][0];
#pragma unroll
            for (int t = 1; t < 16; t++) sum += sm->red[tid][t];
            sm->l_s[tid] = sm->l_s[tid] * sm->alpha_s[tid] + sum;
        }

        // O += P @ V  (inner over 64 keys; a-operand is broadcast LDS)
#pragma unroll 8
        for (int kk = 0; kk < 64; kk++) {
            float4 bb = *(const float4*)&sm->Vs[kk][tx*4];
            float a0 = sm->Ps[ty*4+0][kk];
            float a1 = sm->Ps[ty*4+1][kk];
            float a2 = sm->Ps[ty*4+2][kk];
            float a3 = sm->Ps[ty*4+3][kk];
            o[0][0] += a0*bb.x; o[0][1] += a0*bb.y; o[0][2] += a0*bb.z; o[0][3] += a0*bb.w;
            o[1][0] += a1*bb.x; o[1][1] += a1*bb.y; o[1][2] += a1*bb.z; o[1][3] += a1*bb.w;
            o[2][0] += a2*bb.x; o[2][1] += a2*bb.y; o[2][2] += a2*bb.z; o[2][3] += a2*bb.w;
            o[3][0] += a3*bb.x; o[3][1] += a3*bb.y; o[3][2] += a3*bb.z; o[3][3] += a3*bb.w;
        }
    }
    __syncthreads();

#pragma unroll
    for (int i = 0; i < 4; i++) {
        int r = ty*4 + i;
        float l = sm->l_s[r];
        float inv = (l > 0.f) ? (1.f / l) : 0.f;
        float4 r4 = make_float4(o[i][0]*inv, o[i][1]*inv, o[i][2]*inv, o[i][3]*inv);
        *(float4*)&wv[((size_t)b * S + q0 + r) * DMODEL + h * HD + tx*4] = r4;
    }
}

// ---------------------------------------------------------------------------
// Launch
// Inputs (metadata order): x, mask, position_ids, n_head, Wq, bq, Wk, Wv, bv, Wo, bo
// Outputs (flattened tuple): out [B,S,D], qk [B,H,S,S]
// ---------------------------------------------------------------------------
extern "C" void kernel_launch(void* const* d_in, const int* in_sizes, int n_in,
                              void* d_out, int out_size)
{
    const float* x    = (const float*)d_in[0];
    const int*   mask = (const int*)  d_in[1];
    const int*   pos  = (const int*)  d_in[2];
    const float* Wq   = (const float*)d_in[4];
    const float* bq   = (const float*)d_in[5];
    const float* Wk   = (const float*)d_in[6];
    const float* Wv   = (const float*)d_in[7];
    const float* bv   = (const float*)d_in[8];
    const float* Wo   = (const float*)d_in[9];
    const float* bo   = (const float*)d_in[10];

    const int M = in_sizes[0] / DMODEL;          // B*S
    long long qk_elems = (long long)out_size - (long long)M * DMODEL;
    int S, B;
    if (qk_elems > 0) {
        S = (int)(qk_elems / ((long long)NHEAD * M));
        B = M / S;
    } else {
        S = 2048; B = M / S;
    }

    float* outp = (float*)d_out;
    float* qkp  = (qk_elems > 0) ? outp + (size_t)M * DMODEL : nullptr;

    float *pq, *pk, *pv, *pwv;
    cudaGetSymbolAddress((void**)&pq,  g_q);
    cudaGetSymbolAddress((void**)&pk,  g_k);
    cudaGetSymbolAddress((void**)&pv,  g_v);
    cudaGetSymbolAddress((void**)&pwv, g_wv);

    dim3 gproj(DMODEL / 64, M / 64);
    gemm_tn<<<gproj, 256>>>(x, Wq, bq,      pq, M, DMODEL, DMODEL);
    gemm_tn<<<gproj, 256>>>(x, Wk, nullptr, pk, M, DMODEL, DMODEL);
    gemm_tn<<<gproj, 256>>>(x, Wv, bv,      pv, M, DMODEL, DMODEL);

    int rope_total = M * NHEAD * 32;
    rope_scale_kernel<<<(rope_total + 255) / 256, 256>>>(pq, pk, pos, rope_total);

    int smem = (int)sizeof(AttnSmem);
    cudaFuncSetAttribute(attn_kernel, cudaFuncAttributeMaxDynamicSharedMemorySize, smem);
    dim3 gattn(S / 64, NHEAD, B);
    attn_kernel<<<gattn, 256, smem>>>(pq, pk, pv, mask, qkp, pwv, S);

    gemm_tn<<<gproj, 256>>>(pwv, Wo, bo, outp, M, DMODEL, DMODEL);
}

// round 14
// speedup vs baseline: 1.3116x; 1.3116x over previous
#include <cuda_runtime.h>
#include <cuda_bf16.h>
#include <mma.h>
#include <math.h>

using namespace nvcuda;

// Problem constants (fixed by the dataset: B=2, S=2048, D=1024, H=16, hd=64)
#define DMODEL 1024
#define NHEAD  16
#define HD     64

// Scratch (allocation-free rule: __device__ globals).
__device__ float g_q [4194304];
__device__ float g_k [4194304];
__device__ float g_v [4194304];
__device__ float g_wv[4194304];
// bf16 hi/lo split buffers
__device__ __nv_bfloat16 g_xhi [4194304];
__device__ __nv_bfloat16 g_xlo [4194304];
__device__ __nv_bfloat16 g_whi [4194304];   // Wq|Wk|Wv|Wo, 1M each
__device__ __nv_bfloat16 g_wlo [4194304];
__device__ __nv_bfloat16 g_wvhi[4194304];
__device__ __nv_bfloat16 g_wvlo[4194304];

// ---------------------------------------------------------------------------
// fp32 -> bf16 hi + bf16 lo (residual) split
// ---------------------------------------------------------------------------
__global__ void split_bf16_kernel(const float* __restrict__ src,
                                  __nv_bfloat16* __restrict__ hi,
                                  __nv_bfloat16* __restrict__ lo, int n)
{
    int i = blockIdx.x * blockDim.x + threadIdx.x;
    if (i >= n) return;
    float x = src[i];
    __nv_bfloat16 h = __float2bfloat16(x);
    hi[i] = h;
    lo[i] = __float2bfloat16(x - __bfloat162float(h));
}

// ---------------------------------------------------------------------------
// Tensor-core GEMM: C[M,N] = (Ahi+Alo)[M,K] @ (Bhi+Blo)[N,K]^T  (no bias).
// 128x128 block tile, k-chunk 32, 8 warps (4m x 2n), warp tile 32x64,
// 3-way bf16 split MMA (hi*hi + hi*lo + lo*hi), fp32 accumulators.
// LDS_A=40 element stride: 80B rows -> conflict-free-ish LDSM, and all
// fragment base pointers (rows multiple of 16, ks in {0,16}) are 32B aligned.
// ---------------------------------------------------------------------------
#define LDS_A 40

__global__ __launch_bounds__(256) void gemm_bf16split(
    const __nv_bfloat16* __restrict__ Ahi, const __nv_bfloat16* __restrict__ Alo,
    const __nv_bfloat16* __restrict__ Bhi, const __nv_bfloat16* __restrict__ Blo,
    float* __restrict__ C, int M, int N, int K)
{
    __shared__ __nv_bfloat16 sAh[128 * LDS_A];
    __shared__ __nv_bfloat16 sAl[128 * LDS_A];
    __shared__ __nv_bfloat16 sBh[128 * LDS_A];
    __shared__ __nv_bfloat16 sBl[128 * LDS_A];

    const int tid = threadIdx.x;
    const int m0 = blockIdx.y * 128;
    const int n0 = blockIdx.x * 128;
    const int warp = tid >> 5;
    const int wm = warp >> 1;      // 0..3
    const int wn = warp & 1;       // 0..1

    wmma::fragment<wmma::accumulator, 16, 16, 16, float> acc[2][4];
#pragma unroll
    for (int i = 0; i < 2; i++)
#pragma unroll
        for (int j = 0; j < 4; j++) wmma::fill_fragment(acc[i][j], 0.f);

    for (int k0 = 0; k0 < K; k0 += 32) {
        __syncthreads();
#pragma unroll
        for (int u = 0; u < 2; u++) {
            int id  = tid + u * 256;       // 0..511
            int row = id >> 2;             // 0..127
            int c8  = (id & 3) << 3;       // 0,8,16,24
            size_t ga = (size_t)(m0 + row) * K + k0 + c8;
            size_t gb = (size_t)(n0 + row) * K + k0 + c8;
            int sa = row * LDS_A + c8;
            *(uint4*)&sAh[sa] = *(const uint4*)&Ahi[ga];
            *(uint4*)&sAl[sa] = *(const uint4*)&Alo[ga];
            *(uint4*)&sBh[sa] = *(const uint4*)&Bhi[gb];
            *(uint4*)&sBl[sa] = *(const uint4*)&Blo[gb];
        }
        __syncthreads();

#pragma unroll
        for (int ks = 0; ks < 32; ks += 16) {
            wmma::fragment<wmma::matrix_a, 16, 16, 16, __nv_bfloat16, wmma::row_major> ah[2], al[2];
#pragma unroll
            for (int i = 0; i < 2; i++) {
                int r = wm * 32 + i * 16;
                wmma::load_matrix_sync(ah[i], &sAh[r * LDS_A + ks], LDS_A);
                wmma::load_matrix_sync(al[i], &sAl[r * LDS_A + ks], LDS_A);
            }
#pragma unroll
            for (int j = 0; j < 4; j++) {
                int r = wn * 64 + j * 16;
                wmma::fragment<wmma::matrix_b, 16, 16, 16, __nv_bfloat16, wmma::col_major> bh, bl;
                wmma::load_matrix_sync(bh, &sBh[r * LDS_A + ks], LDS_A);
                wmma::load_matrix_sync(bl, &sBl[r * LDS_A + ks], LDS_A);
#pragma unroll
                for (int i = 0; i < 2; i++) {
                    wmma::mma_sync(acc[i][j], ah[i], bh, acc[i][j]);
                    wmma::mma_sync(acc[i][j], ah[i], bl, acc[i][j]);
                    wmma::mma_sync(acc[i][j], al[i], bh, acc[i][j]);
                }
            }
        }
    }

#pragma unroll
    for (int i = 0; i < 2; i++)
#pragma unroll
        for (int j = 0; j < 4; j++)
            wmma::store_matrix_sync(
                &C[(size_t)(m0 + wm * 32 + i * 16) * N + n0 + wn * 64 + j * 16],
                acc[i][j], N, wmma::mem_row_major);
}

// ---------------------------------------------------------------------------
// RoPE + hd^-0.25 scaling; q gets its bias (bq) added here (GEMM is biasless).
// ---------------------------------------------------------------------------
__global__ void rope_scale_kernel(float* __restrict__ q, float* __restrict__ k,
                                  const int* __restrict__ pos,
                                  const float* __restrict__ bq, int total)
{
    int idx = blockIdx.x * blockDim.x + threadIdx.x;
    if (idx >= total) return;
    int i = idx & 31;
    int h = (idx >> 5) & (NHEAD - 1);
    int m = idx >> 9;

    int p = pos[m];
    float freq = (float)p * exp2f(-(float)i * 0.4152410118609203f);
    float sn, cs;
    sincosf(freq, &sn, &cs);
    const float scale = 0.35355339059327373f;   // 64^-0.25

    size_t base = (size_t)m * DMODEL + h * HD + i;
    float q0 = q[base]      + bq[h * HD + i];
    float q1 = q[base + 32] + bq[h * HD + i + 32];
    q[base]      = (q0 * cs - q1 * sn) * scale;
    q[base + 32] = (q1 * cs + q0 * sn) * scale;
    float k0 = k[base], k1 = k[base + 32];
    k[base]      = (k0 * cs - k1 * sn) * scale;
    k[base + 32] = (k1 * cs + k0 * sn) * scale;
}

// ---------------------------------------------------------------------------
// Flash-style attention (unchanged except: V bias bv added at tile load).
// ---------------------------------------------------------------------------
struct AttnSmem {
    float Qt[64][64];
    float Kt[64][64];
    float Vs[64][64];
    float Ps[64][64];
    float red[64][17];
    float m_s[64], l_s[64], alpha_s[64];
    int   msk[64];
};

__global__ __launch_bounds__(256) void attn_kernel(
    const float* __restrict__ qg, const float* __restrict__ kg,
    const float* __restrict__ vg, const int* __restrict__ mask,
    const float* __restrict__ bv,
    float* __restrict__ qk, float* __restrict__ wv, int S)
{
    extern __shared__ char smraw[];
    AttnSmem* sm = (AttnSmem*)smraw;

    const int tid = threadIdx.x;
    const int tx = tid & 15;
    const int ty = tid >> 4;
    const int b  = blockIdx.z;
    const int h  = blockIdx.y;
    const int q0 = blockIdx.x * 64;

    size_t baseQ = ((size_t)b * S + q0) * DMODEL + h * HD;
#pragma unroll
    for (int it = 0; it < 4; it++) {
        int e  = tid + it * 256;
        int r  = e >> 4;
        int c4 = (e & 15) << 2;
        float4 v4 = *(const float4*)(qg + baseQ + (size_t)r * DMODEL + c4);
        sm->Qt[c4+0][r] = v4.x; sm->Qt[c4+1][r] = v4.y;
        sm->Qt[c4+2][r] = v4.z; sm->Qt[c4+3][r] = v4.w;
    }
    if (tid < 64) { sm->m_s[tid] = -INFINITY; sm->l_s[tid] = 0.f; }

    float o[4][4];
#pragma unroll
    for (int i = 0; i < 4; i++)
#pragma unroll
        for (int j = 0; j < 4; j++) o[i][j] = 0.f;

    for (int kt = 0; kt < S; kt += 64) {
        __syncthreads();
        size_t baseKV = ((size_t)b * S + kt) * DMODEL + h * HD;
#pragma unroll
        for (int it = 0; it < 4; it++) {
            int e  = tid + it * 256;
            int r  = e >> 4;
            int c4 = (e & 15) << 2;
            float4 k4 = *(const float4*)(kg + baseKV + (size_t)r * DMODEL + c4);
            sm->Kt[c4+0][r] = k4.x; sm->Kt[c4+1][r] = k4.y;
            sm->Kt[c4+2][r] = k4.z; sm->Kt[c4+3][r] = k4.w;
            float4 v4 = *(const float4*)(vg + baseKV + (size_t)r * DMODEL + c4);
            float4 bb = *(const float4*)(bv + h * HD + c4);
            v4.x += bb.x; v4.y += bb.y; v4.z += bb.z; v4.w += bb.w;
            *(float4*)&sm->Vs[r][c4] = v4;
        }
        if (tid < 64) sm->msk[tid] = mask[(size_t)b * S + kt + tid];
        __syncthreads();

        float s[4][4];
#pragma unroll
        for (int i = 0; i < 4; i++)
#pragma unroll
            for (int j = 0; j < 4; j++) s[i][j] = 0.f;
#pragma unroll 8
        for (int d = 0; d < 64; d++) {
            float4 a  = *(const float4*)&sm->Qt[d][ty*4];
            float4 bb = *(const float4*)&sm->Kt[d][tx*4];
            s[0][0] += a.x*bb.x; s[0][1] += a.x*bb.y; s[0][2] += a.x*bb.z; s[0][3] += a.x*bb.w;
            s[1][0] += a.y*bb.x; s[1][1] += a.y*bb.y; s[1][2] += a.y*bb.z; s[1][3] += a.y*bb.w;
            s[2][0] += a.z*bb.x; s[2][1] += a.z*bb.y; s[2][2] += a.z*bb.z; s[2][3] += a.z*bb.w;
            s[3][0] += a.w*bb.x; s[3][1] += a.w*bb.y; s[3][2] += a.w*bb.z; s[3][3] += a.w*bb.w;
        }

#pragma unroll
        for (int i = 0; i < 4; i++) {
            float pm = -INFINITY;
#pragma unroll
            for (int j = 0; j < 4; j++) {
                if (sm->msk[tx*4 + j] == 0) s[i][j] = -INFINITY;
                pm = fmaxf(pm, s[i][j]);
            }
            if (qk) {
                size_t qr = (size_t)q0 + ty*4 + i;
                *(float4*)&qk[(((size_t)(b * NHEAD + h)) * S + qr) * S + kt + tx*4] =
                    make_float4(s[i][0], s[i][1], s[i][2], s[i][3]);
            }
            sm->red[ty*4 + i][tx] = pm;
        }
        __syncthreads();

        if (tid < 64) {
            float mx = sm->red[tid][0];
#pragma unroll
            for (int t = 1; t < 16; t++) mx = fmaxf(mx, sm->red[tid][t]);
            float mo = sm->m_s[tid];
            float mn = fmaxf(mo, mx);
            sm->alpha_s[tid] = (mo == -INFINITY) ? 0.f : __expf(mo - mn);
            sm->m_s[tid] = mn;
        }
        __syncthreads();

#pragma unroll
        for (int i = 0; i < 4; i++) {
            int r = ty*4 + i;
            float mn = sm->m_s[r];
            float msub = (mn == -INFINITY) ? 0.f : mn;
            float al = sm->alpha_s[r];
            float p0 = __expf(s[i][0] - msub);
            float p1 = __expf(s[i][1] - msub);
            float p2 = __expf(s[i][2] - msub);
            float p3 = __expf(s[i][3] - msub);
            *(float4*)&sm->Ps[r][tx*4] = make_float4(p0, p1, p2, p3);
            sm->red[r][tx] = p0 + p1 + p2 + p3;
            o[i][0] *= al; o[i][1] *= al; o[i][2] *= al; o[i][3] *= al;
        }
        __syncthreads();

        if (tid < 64) {
            float sum = sm->red[tid][0];
#pragma unroll
            for (int t = 1; t < 16; t++) sum += sm->red[tid][t];
            sm->l_s[tid] = sm->l_s[tid] * sm->alpha_s[tid] + sum;
        }

#pragma unroll 8
        for (int kk = 0; kk < 64; kk++) {
            float4 bb = *(const float4*)&sm->Vs[kk][tx*4];
            float a0 = sm->Ps[ty*4+0][kk];
            float a1 = sm->Ps[ty*4+1][kk];
            float a2 = sm->Ps[ty*4+2][kk];
            float a3 = sm->Ps[ty*4+3][kk];
            o[0][0] += a0*bb.x; o[0][1] += a0*bb.y; o[0][2] += a0*bb.z; o[0][3] += a0*bb.w;
            o[1][0] += a1*bb.x; o[1][1] += a1*bb.y; o[1][2] += a1*bb.z; o[1][3] += a1*bb.w;
            o[2][0] += a2*bb.x; o[2][1] += a2*bb.y; o[2][2] += a2*bb.z; o[2][3] += a2*bb.w;
            o[3][0] += a3*bb.x; o[3][1] += a3*bb.y; o[3][2] += a3*bb.z; o[3][3] += a3*bb.w;
        }
    }
    __syncthreads();

#pragma unroll
    for (int i = 0; i < 4; i++) {
        int r = ty*4 + i;
        float l = sm->l_s[r];
        float inv = (l > 0.f) ? (1.f / l) : 0.f;
        float4 r4 = make_float4(o[i][0]*inv, o[i][1]*inv, o[i][2]*inv, o[i][3]*inv);
        *(float4*)&wv[((size_t)b * S + q0 + r) * DMODEL + h * HD + tx*4] = r4;
    }
}

// ---------------------------------------------------------------------------
// out[i] += bo[i % DMODEL]
// ---------------------------------------------------------------------------
__global__ void bias_add_kernel(float* __restrict__ out,
                                const float* __restrict__ bo, int n)
{
    int i = blockIdx.x * blockDim.x + threadIdx.x;
    if (i >= n) return;
    out[i] += bo[i & (DMODEL - 1)];
}

// ---------------------------------------------------------------------------
// Launch
// Inputs: x, mask, position_ids, n_head, Wq, bq, Wk, Wv, bv, Wo, bo
// Outputs (flattened tuple): out [B,S,D], qk [B,H,S,S]
// ---------------------------------------------------------------------------
extern "C" void kernel_launch(void* const* d_in, const int* in_sizes, int n_in,
                              void* d_out, int out_size)
{
    const float* x    = (const float*)d_in[0];
    const int*   mask = (const int*)  d_in[1];
    const int*   pos  = (const int*)  d_in[2];
    const float* Wq   = (const float*)d_in[4];
    const float* bq   = (const float*)d_in[5];
    const float* Wk   = (const float*)d_in[6];
    const float* Wv   = (const float*)d_in[7];
    const float* bv   = (const float*)d_in[8];
    const float* Wo   = (const float*)d_in[9];
    const float* bo   = (const float*)d_in[10];

    const int M = in_sizes[0] / DMODEL;          // B*S
    long long qk_elems = (long long)out_size - (long long)M * DMODEL;
    int S, B;
    if (qk_elems > 0) {
        S = (int)(qk_elems / ((long long)NHEAD * M));
        B = M / S;
    } else {
        S = 2048; B = M / S;
    }

    float* outp = (float*)d_out;
    float* qkp  = (qk_elems > 0) ? outp + (size_t)M * DMODEL : nullptr;

    float *pq, *pk, *pv, *pwv;
    cudaGetSymbolAddress((void**)&pq,  g_q);
    cudaGetSymbolAddress((void**)&pk,  g_k);
    cudaGetSymbolAddress((void**)&pv,  g_v);
    cudaGetSymbolAddress((void**)&pwv, g_wv);
    __nv_bfloat16 *xhi, *xlo, *whi, *wlo, *wvhi, *wvlo;
    cudaGetSymbolAddress((void**)&xhi,  g_xhi);
    cudaGetSymbolAddress((void**)&xlo,  g_xlo);
    cudaGetSymbolAddress((void**)&whi,  g_whi);
    cudaGetSymbolAddress((void**)&wlo,  g_wlo);
    cudaGetSymbolAddress((void**)&wvhi, g_wvhi);
    cudaGetSymbolAddress((void**)&wvlo, g_wvlo);

    const int nx = M * DMODEL;
    const int nw = DMODEL * DMODEL;

    // Split inputs to bf16 hi/lo
    split_bf16_kernel<<<(nx + 255) / 256, 256>>>(x,  xhi, xlo, nx);
    split_bf16_kernel<<<(nw + 255) / 256, 256>>>(Wq, whi + 0 * nw, wlo + 0 * nw, nw);
    split_bf16_kernel<<<(nw + 255) / 256, 256>>>(Wk, whi + 1 * nw, wlo + 1 * nw, nw);
    split_bf16_kernel<<<(nw + 255) / 256, 256>>>(Wv, whi + 2 * nw, wlo + 2 * nw, nw);
    split_bf16_kernel<<<(nw + 255) / 256, 256>>>(Wo, whi + 3 * nw, wlo + 3 * nw, nw);

    // Tensor-core projections (biasless)
    dim3 gproj(DMODEL / 128, M / 128);
    gemm_bf16split<<<gproj, 256>>>(xhi, xlo, whi + 0 * nw, wlo + 0 * nw, pq, M, DMODEL, DMODEL);
    gemm_bf16split<<<gproj, 256>>>(xhi, xlo, whi + 1 * nw, wlo + 1 * nw, pk, M, DMODEL, DMODEL);
    gemm_bf16split<<<gproj, 256>>>(xhi, xlo, whi + 2 * nw, wlo + 2 * nw, pv, M, DMODEL, DMODEL);

    // RoPE + scale (adds bq)
    int rope_total = M * NHEAD * 32;
    rope_scale_kernel<<<(rope_total + 255) / 256, 256>>>(pq, pk, pos, bq, rope_total);

    // Attention (adds bv on V load), streams qk, writes wv
    int smem = (int)sizeof(AttnSmem);
    cudaFuncSetAttribute(attn_kernel, cudaFuncAttributeMaxDynamicSharedMemorySize, smem);
    dim3 gattn(S / 64, NHEAD, B);
    attn_kernel<<<gattn, 256, smem>>>(pq, pk, pv, mask, bv, qkp, pwv, S);

    // Output projection + bias
    split_bf16_kernel<<<(nx + 255) / 256, 256>>>(pwv, wvhi, wvlo, nx);
    gemm_bf16split<<<gproj, 256>>>(wvhi, wvlo, whi + 3 * nw, wlo + 3 * nw, outp, M, DMODEL, DMODEL);
    bias_add_kernel<<<(nx + 255) / 256, 256>>>(outp, bo, nx);
}